// round 11
// baseline (speedup 1.0000x reference)
#include <cuda_runtime.h>
#include <cuda_bf16.h>
#include <stdint.h>

#define D             128
#define TWO_D         256
#define WARPS         8
#define THREADS       (WARPS * 32)
#define BLOCKS        760              // 152 SMs x 5 blocks/SM -> single full wave
#define TOTAL_WARPS   (BLOCKS * WARPS) // 6080
#define UNROLL        4
#define PF_DIST       12               // prefetch distance in rows (3 iterations ahead)

__global__ void zero_out_kernel(float4* __restrict__ out, int n4) {
    int i = blockIdx.x * blockDim.x + threadIdx.x;
    if (i < n4) out[i] = make_float4(0.f, 0.f, 0.f, 0.f);
}

__device__ __forceinline__ void flush_acc(float* __restrict__ out, int b, int lane4,
                                          float4& a0, float4& a1) {
    float* p0 = out + (size_t)b * TWO_D + lane4;
    atomicAdd(p0 + 0, a0.x);
    atomicAdd(p0 + 1, a0.y);
    atomicAdd(p0 + 2, a0.z);
    atomicAdd(p0 + 3, a0.w);
    float* p1 = p0 + D;
    atomicAdd(p1 + 0, a1.x);
    atomicAdd(p1 + 1, a1.y);
    atomicAdd(p1 + 2, a1.z);
    atomicAdd(p1 + 3, a1.w);
    a0 = make_float4(0.f, 0.f, 0.f, 0.f);
    a1 = make_float4(0.f, 0.f, 0.f, 0.f);
}

__global__ __launch_bounds__(THREADS, 5)
void pool_kernel(const float* __restrict__ node_rep,
                 const int*   __restrict__ batch_ids,
                 const int*   __restrict__ mol_idx,
                 float*       __restrict__ out,
                 int n_rows,
                 int rows_per_warp) {         // multiple of 4
    const int warp  = threadIdx.x >> 5;
    const int lane  = threadIdx.x & 31;
    const int lane4 = lane << 2;

    // perfectly balanced: one contiguous 4-aligned chunk per warp, single wave
    const int gwarp = blockIdx.x * WARPS + warp;
    int cs = gwarp * rows_per_warp;
    int ce = cs + rows_per_warp;
    if (cs >= n_rows) return;
    if (ce > n_rows) ce = n_rows;

    float4 acc0 = make_float4(0.f, 0.f, 0.f, 0.f);
    float4 acc1 = make_float4(0.f, 0.f, 0.f, 0.f);
    int cur_b = -1;

    const float4* nr = reinterpret_cast<const float4*>(node_rep);

    int r = cs;
    for (; r + (UNROLL - 1) < ce; r += UNROLL) {
        // L2 prefetch: lanes 0-15 each fetch one distinct 128B line,
        // covering rows r+PF_DIST .. r+PF_DIST+3 (4 rows x 4 lines).
        // No result register, no scoreboard -> free DRAM-queue occupancy.
        if (lane < 16 && (r + PF_DIST + UNROLL) <= n_rows) {
            const float* pf = node_rep
                + (size_t)(r + PF_DIST + (lane >> 2)) * D
                + (size_t)(lane & 3) * 32;          // 32 floats = 128B line
            asm volatile("prefetch.global.L2 [%0];" :: "l"(pf));
        }

        const int4 bb = __ldg(reinterpret_cast<const int4*>(batch_ids + r));
        const int4 mm = __ldg(reinterpret_cast<const int4*>(mol_idx   + r));
        // streaming (evict-first) reads: node_rep is strictly read-once
        const float4 v0 = __ldcs(nr + (size_t)(r + 0) * (D / 4) + lane);
        const float4 v1 = __ldcs(nr + (size_t)(r + 1) * (D / 4) + lane);
        const float4 v2 = __ldcs(nr + (size_t)(r + 2) * (D / 4) + lane);
        const float4 v3 = __ldcs(nr + (size_t)(r + 3) * (D / 4) + lane);

        if (bb.x != cur_b) { if (cur_b >= 0) flush_acc(out, cur_b, lane4, acc0, acc1); cur_b = bb.x; }
        if (mm.x == 0) { acc0.x += v0.x; acc0.y += v0.y; acc0.z += v0.z; acc0.w += v0.w; }
        else           { acc1.x += v0.x; acc1.y += v0.y; acc1.z += v0.z; acc1.w += v0.w; }

        if (bb.y != cur_b) { flush_acc(out, cur_b, lane4, acc0, acc1); cur_b = bb.y; }
        if (mm.y == 0) { acc0.x += v1.x; acc0.y += v1.y; acc0.z += v1.z; acc0.w += v1.w; }
        else           { acc1.x += v1.x; acc1.y += v1.y; acc1.z += v1.z; acc1.w += v1.w; }

        if (bb.z != cur_b) { flush_acc(out, cur_b, lane4, acc0, acc1); cur_b = bb.z; }
        if (mm.z == 0) { acc0.x += v2.x; acc0.y += v2.y; acc0.z += v2.z; acc0.w += v2.w; }
        else           { acc1.x += v2.x; acc1.y += v2.y; acc1.z += v2.z; acc1.w += v2.w; }

        if (bb.w != cur_b) { flush_acc(out, cur_b, lane4, acc0, acc1); cur_b = bb.w; }
        if (mm.w == 0) { acc0.x += v3.x; acc0.y += v3.y; acc0.z += v3.z; acc0.w += v3.w; }
        else           { acc1.x += v3.x; acc1.y += v3.y; acc1.z += v3.z; acc1.w += v3.w; }
    }
    for (; r < ce; r++) {
        const int b = __ldg(batch_ids + r);
        const int m = __ldg(mol_idx   + r);
        const float4 v = __ldcs(nr + (size_t)r * (D / 4) + lane);
        if (b != cur_b) { if (cur_b >= 0) flush_acc(out, cur_b, lane4, acc0, acc1); cur_b = b; }
        if (m == 0) { acc0.x += v.x; acc0.y += v.y; acc0.z += v.z; acc0.w += v.w; }
        else        { acc1.x += v.x; acc1.y += v.y; acc1.z += v.z; acc1.w += v.w; }
    }

    if (cur_b >= 0) flush_acc(out, cur_b, lane4, acc0, acc1);
}

extern "C" void kernel_launch(void* const* d_in, const int* in_sizes, int n_in,
                              void* d_out, int out_size) {
    const float* node_rep  = (const float*)d_in[0];
    const int*   batch_ids = (const int*)  d_in[1];
    const int*   mol_idx   = (const int*)  d_in[2];
    float*       out       = (float*)      d_out;

    const int n_rows = in_sizes[1];

    // rows per warp: balanced across TOTAL_WARPS, rounded up to multiple of 4
    int rpw = (n_rows + TOTAL_WARPS - 1) / TOTAL_WARPS;
    rpw = (rpw + 3) & ~3;

    {
        int n4 = out_size / 4;
        int threads = 256;
        int blocks  = (n4 + threads - 1) / threads;
        zero_out_kernel<<<blocks, threads>>>((float4*)out, n4);
    }
    pool_kernel<<<BLOCKS, THREADS>>>(node_rep, batch_ids, mol_idx, out, n_rows, rpw);
}

// round 12
// speedup vs baseline: 1.1132x; 1.1132x over previous
#include <cuda_runtime.h>
#include <cuda_bf16.h>
#include <stdint.h>

#define D             128
#define TWO_D         256
#define WARPS         8
#define THREADS       (WARPS * 32)
#define BLOCKS        760              // 152 SMs x 5 blocks/SM -> single full wave
#define TOTAL_WARPS   (BLOCKS * WARPS) // 6080
#define UNROLL        4

__global__ void zero_out_kernel(float4* __restrict__ out, int n4) {
    int i = blockIdx.x * blockDim.x + threadIdx.x;
    if (i < n4) out[i] = make_float4(0.f, 0.f, 0.f, 0.f);
}

__device__ __forceinline__ void flush_acc(float* __restrict__ out, int b, int lane4,
                                          float4& a0, float4& a1) {
    float* p0 = out + (size_t)b * TWO_D + lane4;
    atomicAdd(p0 + 0, a0.x);
    atomicAdd(p0 + 1, a0.y);
    atomicAdd(p0 + 2, a0.z);
    atomicAdd(p0 + 3, a0.w);
    float* p1 = p0 + D;
    atomicAdd(p1 + 0, a1.x);
    atomicAdd(p1 + 1, a1.y);
    atomicAdd(p1 + 2, a1.z);
    atomicAdd(p1 + 3, a1.w);
    a0 = make_float4(0.f, 0.f, 0.f, 0.f);
    a1 = make_float4(0.f, 0.f, 0.f, 0.f);
}

__global__ __launch_bounds__(THREADS, 5)
void pool_kernel(const float* __restrict__ node_rep,
                 const int*   __restrict__ batch_ids,
                 const int*   __restrict__ mol_idx,
                 float*       __restrict__ out,
                 int n_rows,
                 int rows_per_warp) {         // multiple of 4
    const int warp  = threadIdx.x >> 5;
    const int lane  = threadIdx.x & 31;
    const int lane4 = lane << 2;

    // perfectly balanced: one contiguous 4-aligned chunk per warp, single wave
    const int gwarp = blockIdx.x * WARPS + warp;
    int cs = gwarp * rows_per_warp;
    int ce = cs + rows_per_warp;
    if (cs >= n_rows) return;
    if (ce > n_rows) ce = n_rows;

    float4 acc0 = make_float4(0.f, 0.f, 0.f, 0.f);
    float4 acc1 = make_float4(0.f, 0.f, 0.f, 0.f);
    int cur_b = -1;

    const float4* nr = reinterpret_cast<const float4*>(node_rep);

    int r = cs;
    for (; r + (UNROLL - 1) < ce; r += UNROLL) {
        const int4 bb = __ldg(reinterpret_cast<const int4*>(batch_ids + r));
        const int4 mm = __ldg(reinterpret_cast<const int4*>(mol_idx   + r));
        // streaming (evict-first) reads: node_rep is strictly read-once
        const float4 v0 = __ldcs(nr + (size_t)(r + 0) * (D / 4) + lane);
        const float4 v1 = __ldcs(nr + (size_t)(r + 1) * (D / 4) + lane);
        const float4 v2 = __ldcs(nr + (size_t)(r + 2) * (D / 4) + lane);
        const float4 v3 = __ldcs(nr + (size_t)(r + 3) * (D / 4) + lane);

        if (bb.x != cur_b) { if (cur_b >= 0) flush_acc(out, cur_b, lane4, acc0, acc1); cur_b = bb.x; }
        if (mm.x == 0) { acc0.x += v0.x; acc0.y += v0.y; acc0.z += v0.z; acc0.w += v0.w; }
        else           { acc1.x += v0.x; acc1.y += v0.y; acc1.z += v0.z; acc1.w += v0.w; }

        if (bb.y != cur_b) { flush_acc(out, cur_b, lane4, acc0, acc1); cur_b = bb.y; }
        if (mm.y == 0) { acc0.x += v1.x; acc0.y += v1.y; acc0.z += v1.z; acc0.w += v1.w; }
        else           { acc1.x += v1.x; acc1.y += v1.y; acc1.z += v1.z; acc1.w += v1.w; }

        if (bb.z != cur_b) { flush_acc(out, cur_b, lane4, acc0, acc1); cur_b = bb.z; }
        if (mm.z == 0) { acc0.x += v2.x; acc0.y += v2.y; acc0.z += v2.z; acc0.w += v2.w; }
        else           { acc1.x += v2.x; acc1.y += v2.y; acc1.z += v2.z; acc1.w += v2.w; }

        if (bb.w != cur_b) { flush_acc(out, cur_b, lane4, acc0, acc1); cur_b = bb.w; }
        if (mm.w == 0) { acc0.x += v3.x; acc0.y += v3.y; acc0.z += v3.z; acc0.w += v3.w; }
        else           { acc1.x += v3.x; acc1.y += v3.y; acc1.z += v3.z; acc1.w += v3.w; }
    }
    for (; r < ce; r++) {
        const int b = __ldg(batch_ids + r);
        const int m = __ldg(mol_idx   + r);
        const float4 v = __ldcs(nr + (size_t)r * (D / 4) + lane);
        if (b != cur_b) { if (cur_b >= 0) flush_acc(out, cur_b, lane4, acc0, acc1); cur_b = b; }
        if (m == 0) { acc0.x += v.x; acc0.y += v.y; acc0.z += v.z; acc0.w += v.w; }
        else        { acc1.x += v.x; acc1.y += v.y; acc1.z += v.z; acc1.w += v.w; }
    }

    if (cur_b >= 0) flush_acc(out, cur_b, lane4, acc0, acc1);
}

extern "C" void kernel_launch(void* const* d_in, const int* in_sizes, int n_in,
                              void* d_out, int out_size) {
    const float* node_rep  = (const float*)d_in[0];
    const int*   batch_ids = (const int*)  d_in[1];
    const int*   mol_idx   = (const int*)  d_in[2];
    float*       out       = (float*)      d_out;

    const int n_rows = in_sizes[1];

    // rows per warp: balanced across TOTAL_WARPS, rounded up to multiple of 4
    int rpw = (n_rows + TOTAL_WARPS - 1) / TOTAL_WARPS;
    rpw = (rpw + 3) & ~3;

    {
        int n4 = out_size / 4;
        int threads = 256;
        int blocks  = (n4 + threads - 1) / threads;
        zero_out_kernel<<<blocks, threads>>>((float4*)out, n4);
    }
    pool_kernel<<<BLOCKS, THREADS>>>(node_rep, batch_ids, mol_idx, out, n_rows, rpw);
}

// round 13
// speedup vs baseline: 1.1543x; 1.0370x over previous
#include <cuda_runtime.h>
#include <cuda_bf16.h>
#include <stdint.h>

#define D             128
#define TWO_D         256
#define WARPS         8
#define THREADS       (WARPS * 32)
#define BLOCKS        760              // 152 SMs x 5 blocks/SM -> single full wave
#define TOTAL_WARPS   (BLOCKS * WARPS) // 6080
#define UNROLL        5

__global__ void zero_out_kernel(float4* __restrict__ out, int n4) {
    int i = blockIdx.x * blockDim.x + threadIdx.x;
    if (i < n4) out[i] = make_float4(0.f, 0.f, 0.f, 0.f);
}

__device__ __forceinline__ void flush_acc(float* __restrict__ out, int b, int lane4,
                                          float4& a0, float4& a1) {
    float* p0 = out + (size_t)b * TWO_D + lane4;
    atomicAdd(p0 + 0, a0.x);
    atomicAdd(p0 + 1, a0.y);
    atomicAdd(p0 + 2, a0.z);
    atomicAdd(p0 + 3, a0.w);
    float* p1 = p0 + D;
    atomicAdd(p1 + 0, a1.x);
    atomicAdd(p1 + 1, a1.y);
    atomicAdd(p1 + 2, a1.z);
    atomicAdd(p1 + 3, a1.w);
    a0 = make_float4(0.f, 0.f, 0.f, 0.f);
    a1 = make_float4(0.f, 0.f, 0.f, 0.f);
}

__global__ __launch_bounds__(THREADS, 5)
void pool_kernel(const float* __restrict__ node_rep,
                 const int*   __restrict__ batch_ids,
                 const int*   __restrict__ mol_idx,
                 float*       __restrict__ out,
                 int n_rows,
                 int rows_per_warp) {
    const int warp  = threadIdx.x >> 5;
    const int lane  = threadIdx.x & 31;
    const int lane4 = lane << 2;

    // perfectly balanced: one contiguous chunk per warp, single wave
    const int gwarp = blockIdx.x * WARPS + warp;
    int cs = gwarp * rows_per_warp;
    int ce = cs + rows_per_warp;
    if (cs >= n_rows) return;
    if (ce > n_rows) ce = n_rows;

    float4 acc0 = make_float4(0.f, 0.f, 0.f, 0.f);
    float4 acc1 = make_float4(0.f, 0.f, 0.f, 0.f);
    int cur_seg = -1;                   // packed segment id: 2*b + m

    const float4* nr = reinterpret_cast<const float4*>(node_rep);

    int r = cs;
    for (; r + (UNROLL - 1) < ce; r += UNROLL) {
        // packed metadata: one int per row (scalar broadcast loads, L1-resident)
        int seg[UNROLL];
        #pragma unroll
        for (int u = 0; u < UNROLL; u++)
            seg[u] = 2 * __ldg(batch_ids + r + u) + __ldg(mol_idx + r + u);

        // 5 streaming 512B row loads batched -> 7 in-flight loads/warp
        float4 v[UNROLL];
        #pragma unroll
        for (int u = 0; u < UNROLL; u++)
            v[u] = __ldcs(nr + (size_t)(r + u) * (D / 4) + lane);

        #pragma unroll
        for (int u = 0; u < UNROLL; u++) {
            if ((seg[u] >> 1) != (cur_seg >> 1)) {   // graph boundary (rare)
                if (cur_seg >= 0) flush_acc(out, cur_seg >> 1, lane4, acc0, acc1);
            }
            cur_seg = seg[u];
            if ((seg[u] & 1) == 0) {                 // warp-uniform branch
                acc0.x += v[u].x; acc0.y += v[u].y; acc0.z += v[u].z; acc0.w += v[u].w;
            } else {
                acc1.x += v[u].x; acc1.y += v[u].y; acc1.z += v[u].z; acc1.w += v[u].w;
            }
        }
    }
    for (; r < ce; r++) {
        const int s = 2 * __ldg(batch_ids + r) + __ldg(mol_idx + r);
        const float4 v = __ldcs(nr + (size_t)r * (D / 4) + lane);
        if ((s >> 1) != (cur_seg >> 1)) {
            if (cur_seg >= 0) flush_acc(out, cur_seg >> 1, lane4, acc0, acc1);
        }
        cur_seg = s;
        if ((s & 1) == 0) { acc0.x += v.x; acc0.y += v.y; acc0.z += v.z; acc0.w += v.w; }
        else              { acc1.x += v.x; acc1.y += v.y; acc1.z += v.z; acc1.w += v.w; }
    }

    if (cur_seg >= 0) flush_acc(out, cur_seg >> 1, lane4, acc0, acc1);
}

extern "C" void kernel_launch(void* const* d_in, const int* in_sizes, int n_in,
                              void* d_out, int out_size) {
    const float* node_rep  = (const float*)d_in[0];
    const int*   batch_ids = (const int*)  d_in[1];
    const int*   mol_idx   = (const int*)  d_in[2];
    float*       out       = (float*)      d_out;

    const int n_rows = in_sizes[1];

    // rows per warp: balanced across TOTAL_WARPS (no alignment requirement now)
    int rpw = (n_rows + TOTAL_WARPS - 1) / TOTAL_WARPS;

    {
        int n4 = out_size / 4;
        int threads = 256;
        int blocks  = (n4 + threads - 1) / threads;
        zero_out_kernel<<<blocks, threads>>>((float4*)out, n4);
    }
    pool_kernel<<<BLOCKS, THREADS>>>(node_rep, batch_ids, mol_idx, out, n_rows, rpw);
}